// round 12
// baseline (speedup 1.0000x reference)
#include <cuda_runtime.h>
#include <math.h>
#include <stdint.h>

// Problem shape (fixed per reference)
#define NB     2
#define NSEQ   2048
#define DMODEL 1024
#define NINNER 1024
#define NH     16
#define NDH    64
#define MTOT   (NB * NSEQ)   // 4096

// Scratch (allocation-free rule: __device__ globals)
__device__ float g_Q  [MTOT * NINNER];        // 16 MB
__device__ float g_KV [MTOT * 2 * NINNER];    // 32 MB
__device__ float g_A  [MTOT * NINNER];        // 16 MB
__device__ float g_WqT [NINNER * DMODEL];     // 4 MB   [N][K]
__device__ float g_WkvT[2 * NINNER * DMODEL]; // 8 MB   [N][K]
__device__ float g_WoT [DMODEL * NINNER];     // 4 MB   [N][K]

// ===========================================================================
// Helpers (baseline PTX only — ptxas targets sm_103, no 'a' features)
// ===========================================================================
__device__ __forceinline__ uint32_t f2tf32(float x) {
    uint32_t u;
    asm("cvt.rna.tf32.f32 %0, %1;" : "=r"(u) : "f"(x));
    return u;
}

// m16n8k8 tf32 mma, row.col, fp32 accumulate
__device__ __forceinline__ void mma8(float* d, const uint32_t* a,
                                     uint32_t b0, uint32_t b1) {
    asm volatile(
        "mma.sync.aligned.m16n8k8.row.col.f32.tf32.tf32.f32 "
        "{%0,%1,%2,%3}, {%4,%5,%6,%7}, {%8,%9}, {%0,%1,%2,%3};"
        : "+f"(d[0]), "+f"(d[1]), "+f"(d[2]), "+f"(d[3])
        : "r"(a[0]), "r"(a[1]), "r"(a[2]), "r"(a[3]), "r"(b0), "r"(b1));
}

// ===========================================================================
// 32x32 tiled transpose: out[C,R] = in[R,C]^T
// ===========================================================================
__global__ void transpose_kernel(const float* __restrict__ in,
                                 float* __restrict__ out, int R, int C) {
    __shared__ float t[32][33];
    const int bx = blockIdx.x * 32;
    const int by = blockIdx.y * 32;
    #pragma unroll
    for (int i = 0; i < 32; i += 8)
        t[threadIdx.y + i][threadIdx.x] =
            in[(size_t)(by + threadIdx.y + i) * C + bx + threadIdx.x];
    __syncthreads();
    #pragma unroll
    for (int i = 0; i < 32; i += 8)
        out[(size_t)(bx + threadIdx.y + i) * R + by + threadIdx.x] =
            t[threadIdx.x][threadIdx.y + i];
}

// ===========================================================================
// tf32 mma.sync GEMM: C[M,N] = A[M,K] @ Bt[N,K]^T (+bias)
// 128x128x32 CTA tile, 8 warps, double-buffered smem stride 36.
// ===========================================================================
#define GST 36
#define GSTAGE (2 * 128 * GST)
#define GEMM_SMEM_BYTES (2 * GSTAGE * 4)     // 73728

__global__ __launch_bounds__(256, 2) void gemm_mma(
    const float* __restrict__ A, const float* __restrict__ Bt,
    const float* __restrict__ bias, float* __restrict__ C,
    int M, int N, int K)
{
    extern __shared__ uint32_t sm[];
    const int tid  = threadIdx.x;
    const int lane = tid & 31, wid = tid >> 5;
    const int gid  = lane >> 2, tig = lane & 3;
    const int warp_m = wid & 1, warp_n = wid >> 1;
    const int bm = blockIdx.y * 128;
    const int bn = blockIdx.x * 128;

    const int lrow = tid >> 3;
    const int lch  = (tid & 7) << 2;
    const float* Ap = A  + (size_t)(bm + lrow) * K + lch;
    const float* Bp = Bt + (size_t)(bn + lrow) * K + lch;
    const uint32_t sOff = (uint32_t)(lrow * GST + lch);

    float4 ra[4], rb[4];
    const int nkt = K / 32;

    #pragma unroll
    for (int i = 0; i < 4; i++) {
        ra[i] = *(const float4*)(Ap + (size_t)(32 * i) * K);
        rb[i] = *(const float4*)(Bp + (size_t)(32 * i) * K);
    }
    #pragma unroll
    for (int i = 0; i < 4; i++) {
        uint4 va = { f2tf32(ra[i].x), f2tf32(ra[i].y), f2tf32(ra[i].z), f2tf32(ra[i].w) };
        uint4 vb = { f2tf32(rb[i].x), f2tf32(rb[i].y), f2tf32(rb[i].z), f2tf32(rb[i].w) };
        *(uint4*)&sm[sOff + i * 32 * GST]             = va;
        *(uint4*)&sm[128 * GST + sOff + i * 32 * GST] = vb;
    }
    __syncthreads();

    float acc[4][4][4] = {};

    for (int kt = 0; kt < nkt; kt++) {
        const int p = kt & 1;
        if (kt + 1 < nkt) {
            const int k0 = (kt + 1) * 32;
            #pragma unroll
            for (int i = 0; i < 4; i++) {
                ra[i] = *(const float4*)(Ap + (size_t)(32 * i) * K + k0);
                rb[i] = *(const float4*)(Bp + (size_t)(32 * i) * K + k0);
            }
        }

        const uint32_t* sA = sm + p * GSTAGE;
        const uint32_t* sB = sA + 128 * GST;
        #pragma unroll
        for (int ks = 0; ks < 4; ks++) {
            const int col = ks * 8 + tig;
            uint32_t af[4][4];
            #pragma unroll
            for (int im = 0; im < 4; im++) {
                const int base = (warp_m * 64 + im * 16 + gid) * GST + col;
                af[im][0] = sA[base];
                af[im][1] = sA[base + 8 * GST];
                af[im][2] = sA[base + 4];
                af[im][3] = sA[base + 8 * GST + 4];
            }
            uint32_t bf[4][2];
            #pragma unroll
            for (int jn = 0; jn < 4; jn++) {
                const int nb = (warp_n * 32 + jn * 8 + gid) * GST + col;
                bf[jn][0] = sB[nb];
                bf[jn][1] = sB[nb + 4];
            }
            #pragma unroll
            for (int im = 0; im < 4; im++)
                #pragma unroll
                for (int jn = 0; jn < 4; jn++)
                    mma8(acc[im][jn], af[im], bf[jn][0], bf[jn][1]);
        }

        if (kt + 1 < nkt) {
            uint32_t* dA = sm + (p ^ 1) * GSTAGE + sOff;
            uint32_t* dB = dA + 128 * GST;
            #pragma unroll
            for (int i = 0; i < 4; i++) {
                uint4 va = { f2tf32(ra[i].x), f2tf32(ra[i].y), f2tf32(ra[i].z), f2tf32(ra[i].w) };
                uint4 vb = { f2tf32(rb[i].x), f2tf32(rb[i].y), f2tf32(rb[i].z), f2tf32(rb[i].w) };
                *(uint4*)&dA[i * 32 * GST] = va;
                *(uint4*)&dB[i * 32 * GST] = vb;
            }
        }
        __syncthreads();
    }

    #pragma unroll
    for (int im = 0; im < 4; im++) {
        const int row0 = bm + warp_m * 64 + im * 16 + gid;
        #pragma unroll
        for (int jn = 0; jn < 4; jn++) {
            const int col = bn + warp_n * 32 + jn * 8 + 2 * tig;
            float b0 = 0.f, b1 = 0.f;
            if (bias) { b0 = bias[col]; b1 = bias[col + 1]; }
            float2 v0 = { acc[im][jn][0] + b0, acc[im][jn][1] + b1 };
            float2 v1 = { acc[im][jn][2] + b0, acc[im][jn][3] + b1 };
            *(float2*)&C[(size_t)row0 * N + col]       = v0;
            *(float2*)&C[(size_t)(row0 + 8) * N + col] = v1;
        }
    }
}

// ===========================================================================
// tf32 mma.sync flash attention.
// 256 threads (8 warps), CTA = 128 Q rows of one (b,h); warp = 16 rows.
// KEY TILE = 32 (R11): shrinks S regs 32->16 so the full live set
// (qf 32 + o 32 + s 16 + temps) fits the 128-reg cap WITHOUT spills at
// 2 CTAs/SM. Per-key LDS/STS and gmem traffic identical to the 64-key
// version; only barrier and alpha-rescale counts double (negligible).
// Q frags hoisted (32 regs), scale folded into Q. P -> tf32 into retired
// sQ region (warp-private rows). V stride 72: PV B-frag conflict-free.
// smem: sQ/sP 128*68 + sK 32*68 + sV 32*72 = 13184 words = 52736 B.
// ===========================================================================
#define KT  32
#define FST 68
#define VST 72
#define FQP  (128 * FST)
#define FKO  (KT * FST)
#define FLASH_SMEM_BYTES ((FQP + FKO + KT * VST) * 4)   // 52736

__global__ __launch_bounds__(256, 2) void flash_mma(
    const float* __restrict__ Q, const float* __restrict__ KV,
    float* __restrict__ O)
{
    extern __shared__ uint32_t smf[];
    uint32_t* sQ = smf;              // becomes sP after Q frags hoisted
    uint32_t* sK = smf + FQP;
    uint32_t* sV = smf + FQP + FKO;

    const int tid  = threadIdx.x;
    const int lane = tid & 31, wid = tid >> 5;
    const int gid  = lane >> 2, tig = lane & 3;
    const int wrow = wid * 16;
    const int q0   = blockIdx.x * 128;
    const int bh   = blockIdx.y;
    const int b    = bh >> 4;
    const int h    = bh & 15;

    const float* Qb = Q  + (size_t)b * NSEQ * NINNER     + (size_t)h * NDH;
    const float* Kb = KV + (size_t)b * NSEQ * 2 * NINNER + (size_t)h * NDH;
    const float* Vb = Kb + NINNER;
    float*       Ob = O  + (size_t)b * NSEQ * NINNER     + (size_t)h * NDH;

    // load Q tile (128x64) -> tf32 smem, scale folded
    #pragma unroll
    for (int i = 0; i < 8; i++) {
        const int fid = tid + 256 * i;
        const int row = fid >> 4;
        const int c4  = (fid & 15) << 2;
        float4 v = *(const float4*)&Qb[(size_t)(q0 + row) * NINNER + c4];
        uint4 u = { f2tf32(v.x * 0.125f), f2tf32(v.y * 0.125f),
                    f2tf32(v.z * 0.125f), f2tf32(v.w * 0.125f) };
        *(uint4*)&sQ[row * FST + c4] = u;
    }
    __syncthreads();

    // hoist Q fragments for all 8 k-steps (warp's own 16 rows)
    uint32_t qf[8][4];
    {
        const int base = (wrow + gid) * FST;
        #pragma unroll
        for (int ks = 0; ks < 8; ks++) {
            const int w = ks * 8 + tig;
            qf[ks][0] = sQ[base + w];
            qf[ks][1] = sQ[base + 8 * FST + w];
            qf[ks][2] = sQ[base + w + 4];
            qf[ks][3] = sQ[base + 8 * FST + w + 4];
        }
    }

    float o[8][4] = {};
    float mr0 = -INFINITY, mr1 = -INFINITY, lr0 = 0.f, lr1 = 0.f;

    for (int j0 = 0; j0 < NSEQ; j0 += KT) {
        __syncthreads();   // prior iter's sK/sV reads done (also fences hoist)
        // K tile (32x64) -> sK [key][d], stride 68
        #pragma unroll
        for (int i = 0; i < 2; i++) {
            const int fid = tid + 256 * i;
            const int row = fid >> 4;
            const int c4  = (fid & 15) << 2;
            float4 kv = *(const float4*)&Kb[(size_t)(j0 + row) * (2 * NINNER) + c4];
            uint4 u = { f2tf32(kv.x), f2tf32(kv.y), f2tf32(kv.z), f2tf32(kv.w) };
            *(uint4*)&sK[row * FST + c4] = u;
        }
        // V tile (32x64) -> sV [key][d], stride 72
        #pragma unroll
        for (int i = 0; i < 2; i++) {
            const int fid = tid + 256 * i;
            const int row = fid >> 4;
            const int c4  = (fid & 15) << 2;
            float4 vv = *(const float4*)&Vb[(size_t)(j0 + row) * (2 * NINNER) + c4];
            uint4 u = { f2tf32(vv.x), f2tf32(vv.y), f2tf32(vv.z), f2tf32(vv.w) };
            *(uint4*)&sV[row * VST + c4] = u;
        }
        __syncthreads();

        // S = Q @ K^T  (16 rows x 32 keys per warp)
        float s[4][4] = {};
        #pragma unroll
        for (int ks = 0; ks < 8; ks++) {
            #pragma unroll
            for (int jn = 0; jn < 4; jn++) {
                const int kb = (jn * 8 + gid) * FST + ks * 8 + tig;
                mma8(s[jn], qf[ks], sK[kb], sK[kb + 4]);
            }
        }

        // online softmax (rows gid -> c0,c1 ; gid+8 -> c2,c3)
        float mx0 = -INFINITY, mx1 = -INFINITY;
        #pragma unroll
        for (int jn = 0; jn < 4; jn++) {
            mx0 = fmaxf(mx0, fmaxf(s[jn][0], s[jn][1]));
            mx1 = fmaxf(mx1, fmaxf(s[jn][2], s[jn][3]));
        }
        mx0 = fmaxf(mx0, __shfl_xor_sync(0xffffffffu, mx0, 1));
        mx0 = fmaxf(mx0, __shfl_xor_sync(0xffffffffu, mx0, 2));
        mx1 = fmaxf(mx1, __shfl_xor_sync(0xffffffffu, mx1, 1));
        mx1 = fmaxf(mx1, __shfl_xor_sync(0xffffffffu, mx1, 2));

        const float mn0 = fmaxf(mr0, mx0);
        const float mn1 = fmaxf(mr1, mx1);
        const float al0 = __expf(mr0 - mn0);
        const float al1 = __expf(mr1 - mn1);
        mr0 = mn0; mr1 = mn1;

        float rs0 = 0.f, rs1 = 0.f;
        {
            const int pb0 = (wrow + gid) * FST + 2 * tig;
            #pragma unroll
            for (int jn = 0; jn < 4; jn++) {
                const float p0 = __expf(s[jn][0] - mn0);
                const float p1 = __expf(s[jn][1] - mn0);
                const float p2 = __expf(s[jn][2] - mn1);
                const float p3 = __expf(s[jn][3] - mn1);
                rs0 += p0 + p1;
                rs1 += p2 + p3;
                sQ[pb0 + jn * 8]               = f2tf32(p0);   // sP overlays sQ
                sQ[pb0 + jn * 8 + 1]           = f2tf32(p1);
                sQ[pb0 + 8 * FST + jn * 8]     = f2tf32(p2);
                sQ[pb0 + 8 * FST + jn * 8 + 1] = f2tf32(p3);
            }
        }
        rs0 += __shfl_xor_sync(0xffffffffu, rs0, 1);
        rs0 += __shfl_xor_sync(0xffffffffu, rs0, 2);
        rs1 += __shfl_xor_sync(0xffffffffu, rs1, 1);
        rs1 += __shfl_xor_sync(0xffffffffu, rs1, 2);
        lr0 = lr0 * al0 + rs0;
        lr1 = lr1 * al1 + rs1;

        #pragma unroll
        for (int dt = 0; dt < 8; dt++) {
            o[dt][0] *= al0; o[dt][1] *= al0;
            o[dt][2] *= al1; o[dt][3] *= al1;
        }
        __syncwarp();   // P rows are warp-private

        // O += P @ V  (k-dim = 32 keys -> 4 k-steps)
        #pragma unroll
        for (int ks = 0; ks < 4; ks++) {
            uint32_t pa[4];
            const int base = (wrow + gid) * FST + ks * 8 + tig;
            pa[0] = sQ[base];
            pa[1] = sQ[base + 8 * FST];
            pa[2] = sQ[base + 4];
            pa[3] = sQ[base + 8 * FST + 4];
            #pragma unroll
            for (int dt = 0; dt < 8; dt++) {
                const int vb = (ks * 8 + tig) * VST + dt * 8 + gid;
                mma8(o[dt], pa, sV[vb], sV[vb + 4 * VST]);
            }
        }
    }

    // epilogue
    const float inv0 = 1.0f / lr0;
    const float inv1 = 1.0f / lr1;
    const int r0 = q0 + wrow + gid;
    #pragma unroll
    for (int dt = 0; dt < 8; dt++) {
        const int col = dt * 8 + 2 * tig;
        float2 v0 = { o[dt][0] * inv0, o[dt][1] * inv0 };
        float2 v1 = { o[dt][2] * inv1, o[dt][3] * inv1 };
        *(float2*)&Ob[(size_t)r0 * NINNER + col]       = v0;
        *(float2*)&Ob[(size_t)(r0 + 8) * NINNER + col] = v1;
    }
}

// ===========================================================================
extern "C" void kernel_launch(void* const* d_in, const int* in_sizes, int n_in,
                              void* d_out, int out_size)
{
    const float* X   = (const float*)d_in[0];
    const float* Wq  = (const float*)d_in[1];
    const float* Wkv = (const float*)d_in[2];
    const float* Wo  = (const float*)d_in[3];
    const float* bo  = (const float*)d_in[4];
    float* out = (float*)d_out;

    float *Qb, *KVb, *Ab, *WqT, *WkvT, *WoT;
    cudaGetSymbolAddress((void**)&Qb,   g_Q);
    cudaGetSymbolAddress((void**)&KVb,  g_KV);
    cudaGetSymbolAddress((void**)&Ab,   g_A);
    cudaGetSymbolAddress((void**)&WqT,  g_WqT);
    cudaGetSymbolAddress((void**)&WkvT, g_WkvT);
    cudaGetSymbolAddress((void**)&WoT,  g_WoT);

    cudaFuncSetAttribute(gemm_mma, cudaFuncAttributeMaxDynamicSharedMemorySize,
                         GEMM_SMEM_BYTES);
    cudaFuncSetAttribute(flash_mma, cudaFuncAttributeMaxDynamicSharedMemorySize,
                         FLASH_SMEM_BYTES);

    dim3 tb(32, 8);
    transpose_kernel<<<dim3(NINNER / 32, DMODEL / 32), tb>>>(Wq,  WqT,  DMODEL, NINNER);
    transpose_kernel<<<dim3(2 * NINNER / 32, DMODEL / 32), tb>>>(Wkv, WkvT, DMODEL, 2 * NINNER);
    transpose_kernel<<<dim3(DMODEL / 32, NINNER / 32), tb>>>(Wo,  WoT,  NINNER, DMODEL);

    // Q = X @ Wq
    gemm_mma<<<dim3(NINNER / 128, MTOT / 128), 256, GEMM_SMEM_BYTES>>>(
        X, WqT, nullptr, Qb, MTOT, NINNER, DMODEL);
    // KV = X @ Wkv
    gemm_mma<<<dim3(2 * NINNER / 128, MTOT / 128), 256, GEMM_SMEM_BYTES>>>(
        X, WkvT, nullptr, KVb, MTOT, 2 * NINNER, DMODEL);
    // attention
    flash_mma<<<dim3(NSEQ / 128, NB * NH), 256, FLASH_SMEM_BYTES>>>(Qb, KVb, Ab);
    // out = A @ Wo + bo
    gemm_mma<<<dim3(DMODEL / 128, MTOT / 128), 256, GEMM_SMEM_BYTES>>>(
        Ab, WoT, bo, out, MTOT, DMODEL, NINNER);
}

// round 13
// speedup vs baseline: 1.0708x; 1.0708x over previous
#include <cuda_runtime.h>
#include <math.h>
#include <stdint.h>

// Problem shape (fixed per reference)
#define NB     2
#define NSEQ   2048
#define DMODEL 1024
#define NINNER 1024
#define NH     16
#define NDH    64
#define MTOT   (NB * NSEQ)   // 4096

// Scratch (allocation-free rule: __device__ globals)
__device__ float g_Q  [MTOT * NINNER];        // 16 MB  (pre-scaled, tf32-valued)
__device__ float g_KV [MTOT * 2 * NINNER];    // 32 MB  (tf32-valued)
__device__ float g_A  [MTOT * NINNER];        // 16 MB
__device__ float g_WqT [NINNER * DMODEL];     // 4 MB   [N][K], pre-scaled 0.125
__device__ float g_WkvT[2 * NINNER * DMODEL]; // 8 MB   [N][K]
__device__ float g_WoT [DMODEL * NINNER];     // 4 MB   [N][K]

// ===========================================================================
// Helpers (baseline PTX only — ptxas targets sm_103, no 'a' features)
// ===========================================================================
__device__ __forceinline__ uint32_t f2tf32(float x) {
    uint32_t u;
    asm("cvt.rna.tf32.f32 %0, %1;" : "=r"(u) : "f"(x));
    return u;
}
__device__ __forceinline__ uint32_t smem_u32(const void* p) {
    uint32_t a;
    asm("{ .reg .u64 t; cvta.to.shared.u64 t, %1; cvt.u32.u64 %0, t; }"
        : "=r"(a) : "l"(p));
    return a;
}
__device__ __forceinline__ void cpa16(uint32_t dst, const void* src) {
    asm volatile("cp.async.cg.shared.global [%0], [%1], 16;"
                 :: "r"(dst), "l"(src) : "memory");
}
#define CP_COMMIT() asm volatile("cp.async.commit_group;" ::: "memory")

// m16n8k8 tf32 mma, row.col, fp32 accumulate
__device__ __forceinline__ void mma8(float* d, const uint32_t* a,
                                     uint32_t b0, uint32_t b1) {
    asm volatile(
        "mma.sync.aligned.m16n8k8.row.col.f32.tf32.tf32.f32 "
        "{%0,%1,%2,%3}, {%4,%5,%6,%7}, {%8,%9}, {%0,%1,%2,%3};"
        : "+f"(d[0]), "+f"(d[1]), "+f"(d[2]), "+f"(d[3])
        : "r"(a[0]), "r"(a[1]), "r"(a[2]), "r"(a[3]), "r"(b0), "r"(b1));
}

// ===========================================================================
// 32x32 tiled transpose with scale: out[C,R] = in[R,C]^T * scale
// ===========================================================================
__global__ void transpose_kernel(const float* __restrict__ in,
                                 float* __restrict__ out, int R, int C,
                                 float scale) {
    __shared__ float t[32][33];
    const int bx = blockIdx.x * 32;
    const int by = blockIdx.y * 32;
    #pragma unroll
    for (int i = 0; i < 32; i += 8)
        t[threadIdx.y + i][threadIdx.x] =
            in[(size_t)(by + threadIdx.y + i) * C + bx + threadIdx.x] * scale;
    __syncthreads();
    #pragma unroll
    for (int i = 0; i < 32; i += 8)
        out[(size_t)(bx + threadIdx.y + i) * R + by + threadIdx.x] =
            t[threadIdx.x][threadIdx.y + i];
}

// ===========================================================================
// tf32 mma.sync GEMM: C[M,N] = A[M,K] @ Bt[N,K]^T (+bias)
// 128x128x32 CTA tile, 8 warps, double-buffered smem stride 36.
// round_out: store tf32-rounded values (producer-side rounding for flash).
// ===========================================================================
#define GST 36
#define GSTAGE (2 * 128 * GST)
#define GEMM_SMEM_BYTES (2 * GSTAGE * 4)     // 73728

__global__ __launch_bounds__(256, 2) void gemm_mma(
    const float* __restrict__ A, const float* __restrict__ Bt,
    const float* __restrict__ bias, float* __restrict__ C,
    int M, int N, int K, int round_out)
{
    extern __shared__ uint32_t sm[];
    const int tid  = threadIdx.x;
    const int lane = tid & 31, wid = tid >> 5;
    const int gid  = lane >> 2, tig = lane & 3;
    const int warp_m = wid & 1, warp_n = wid >> 1;
    const int bm = blockIdx.y * 128;
    const int bn = blockIdx.x * 128;

    const int lrow = tid >> 3;
    const int lch  = (tid & 7) << 2;
    const float* Ap = A  + (size_t)(bm + lrow) * K + lch;
    const float* Bp = Bt + (size_t)(bn + lrow) * K + lch;
    const uint32_t sOff = (uint32_t)(lrow * GST + lch);

    float4 ra[4], rb[4];
    const int nkt = K / 32;

    #pragma unroll
    for (int i = 0; i < 4; i++) {
        ra[i] = *(const float4*)(Ap + (size_t)(32 * i) * K);
        rb[i] = *(const float4*)(Bp + (size_t)(32 * i) * K);
    }
    #pragma unroll
    for (int i = 0; i < 4; i++) {
        uint4 va = { f2tf32(ra[i].x), f2tf32(ra[i].y), f2tf32(ra[i].z), f2tf32(ra[i].w) };
        uint4 vb = { f2tf32(rb[i].x), f2tf32(rb[i].y), f2tf32(rb[i].z), f2tf32(rb[i].w) };
        *(uint4*)&sm[sOff + i * 32 * GST]             = va;
        *(uint4*)&sm[128 * GST + sOff + i * 32 * GST] = vb;
    }
    __syncthreads();

    float acc[4][4][4] = {};

    for (int kt = 0; kt < nkt; kt++) {
        const int p = kt & 1;
        if (kt + 1 < nkt) {
            const int k0 = (kt + 1) * 32;
            #pragma unroll
            for (int i = 0; i < 4; i++) {
                ra[i] = *(const float4*)(Ap + (size_t)(32 * i) * K + k0);
                rb[i] = *(const float4*)(Bp + (size_t)(32 * i) * K + k0);
            }
        }

        const uint32_t* sA = sm + p * GSTAGE;
        const uint32_t* sB = sA + 128 * GST;
        #pragma unroll
        for (int ks = 0; ks < 4; ks++) {
            const int col = ks * 8 + tig;
            uint32_t af[4][4];
            #pragma unroll
            for (int im = 0; im < 4; im++) {
                const int base = (warp_m * 64 + im * 16 + gid) * GST + col;
                af[im][0] = sA[base];
                af[im][1] = sA[base + 8 * GST];
                af[im][2] = sA[base + 4];
                af[im][3] = sA[base + 8 * GST + 4];
            }
            uint32_t bf[4][2];
            #pragma unroll
            for (int jn = 0; jn < 4; jn++) {
                const int nb = (warp_n * 32 + jn * 8 + gid) * GST + col;
                bf[jn][0] = sB[nb];
                bf[jn][1] = sB[nb + 4];
            }
            #pragma unroll
            for (int im = 0; im < 4; im++)
                #pragma unroll
                for (int jn = 0; jn < 4; jn++)
                    mma8(acc[im][jn], af[im], bf[jn][0], bf[jn][1]);
        }

        if (kt + 1 < nkt) {
            uint32_t* dA = sm + (p ^ 1) * GSTAGE + sOff;
            uint32_t* dB = dA + 128 * GST;
            #pragma unroll
            for (int i = 0; i < 4; i++) {
                uint4 va = { f2tf32(ra[i].x), f2tf32(ra[i].y), f2tf32(ra[i].z), f2tf32(ra[i].w) };
                uint4 vb = { f2tf32(rb[i].x), f2tf32(rb[i].y), f2tf32(rb[i].z), f2tf32(rb[i].w) };
                *(uint4*)&dA[i * 32 * GST] = va;
                *(uint4*)&dB[i * 32 * GST] = vb;
            }
        }
        __syncthreads();
    }

    #pragma unroll
    for (int im = 0; im < 4; im++) {
        const int row0 = bm + warp_m * 64 + im * 16 + gid;
        #pragma unroll
        for (int jn = 0; jn < 4; jn++) {
            const int col = bn + warp_n * 32 + jn * 8 + 2 * tig;
            float b0 = 0.f, b1 = 0.f;
            if (bias) { b0 = bias[col]; b1 = bias[col + 1]; }
            float2 v0 = { acc[im][jn][0] + b0, acc[im][jn][1] + b1 };
            float2 v1 = { acc[im][jn][2] + b0, acc[im][jn][3] + b1 };
            if (round_out) {
                v0.x = __uint_as_float(f2tf32(v0.x));
                v0.y = __uint_as_float(f2tf32(v0.y));
                v1.x = __uint_as_float(f2tf32(v1.x));
                v1.y = __uint_as_float(f2tf32(v1.y));
            }
            *(float2*)&C[(size_t)row0 * N + col]       = v0;
            *(float2*)&C[(size_t)(row0 + 8) * N + col] = v1;
        }
    }
}

// ===========================================================================
// tf32 mma.sync flash attention with cp.async double-buffered K/V.
// 256 threads (8 warps), CTA = 128 Q rows of one (b,h); warp = 16 rows.
// KT=64. Inputs pre-rounded to tf32 values (and Q pre-scaled) by producer
// GEMMs -> no conversion here; K/V tiles stream via cp.async so tile j+1
// copy overlaps tile j compute (gmem latency off the critical path).
// smem: sQ/sP 128*68 + 2 stages of (K 64*68 + V 64*72) = 106496 B.
// ===========================================================================
#define KT  64
#define FST 68
#define VST 72
#define SQW    (128 * FST)             // 8704 words
#define STAGEW (KT * FST + KT * VST)   // 8960 words
#define FLASH_SMEM_BYTES ((SQW + 2 * STAGEW) * 4)   // 106496

__global__ __launch_bounds__(256, 2) void flash_mma(
    const float* __restrict__ Q, const float* __restrict__ KV,
    float* __restrict__ O)
{
    extern __shared__ uint32_t smf[];
    uint32_t* sQ = smf;                 // becomes sP after Q frags hoisted
    const uint32_t smb = smem_u32(smf);

    const int tid  = threadIdx.x;
    const int lane = tid & 31, wid = tid >> 5;
    const int gid  = lane >> 2, tig = lane & 3;
    const int wrow = wid * 16;
    const int q0   = blockIdx.x * 128;
    const int bh   = blockIdx.y;
    const int b    = bh >> 4;
    const int h    = bh & 15;

    const float* Qb = Q  + (size_t)b * NSEQ * NINNER     + (size_t)h * NDH;
    const float* Kb = KV + (size_t)b * NSEQ * 2 * NINNER + (size_t)h * NDH;
    const float* Vb = Kb + NINNER;
    float*       Ob = O  + (size_t)b * NSEQ * NINNER     + (size_t)h * NDH;

    // per-thread chunk coords (16B chunks)
    const int qrow = tid >> 4;           // +32 per rep (Q: 8 reps)
    const int qc4  = (tid & 15) << 2;

    // ---- prologue: async-copy Q (group 0), then K/V tile 0 (group 1) ----
    #pragma unroll
    for (int i = 0; i < 8; i++) {
        const int row = qrow + 16 * i;
        cpa16(smb + (uint32_t)(row * FST + qc4) * 4,
              &Qb[(size_t)(q0 + row) * NINNER + qc4]);
    }
    CP_COMMIT();
    {
        const uint32_t kb0 = smb + SQW * 4;
        const uint32_t vb0 = kb0 + KT * FST * 4;
        #pragma unroll
        for (int i = 0; i < 4; i++) {
            const int row = qrow + 16 * i;
            const size_t g = (size_t)row * (2 * NINNER) + qc4;
            cpa16(kb0 + (uint32_t)(row * FST + qc4) * 4, &Kb[g]);
            cpa16(vb0 + (uint32_t)(row * VST + qc4) * 4, &Vb[g]);
        }
    }
    CP_COMMIT();
    asm volatile("cp.async.wait_group 1;" ::: "memory");   // Q done
    __syncthreads();

    // hoist Q fragments for all 8 k-steps (warp's own 16 rows)
    uint32_t qf[8][4];
    {
        const int base = (wrow + gid) * FST;
        #pragma unroll
        for (int ks = 0; ks < 8; ks++) {
            const int w = ks * 8 + tig;
            qf[ks][0] = sQ[base + w];
            qf[ks][1] = sQ[base + 8 * FST + w];
            qf[ks][2] = sQ[base + w + 4];
            qf[ks][3] = sQ[base + 8 * FST + w + 4];
        }
    }

    float o[8][4] = {};
    float mr0 = -INFINITY, mr1 = -INFINITY, lr0 = 0.f, lr1 = 0.f;

    int stage = 0;
    for (int j0 = 0; j0 < NSEQ; j0 += KT) {
        __syncthreads();   // all warps done with buffer stage^1 (tile j-1)
        if (j0 + KT < NSEQ) {
            const uint32_t kbn = smb + (SQW + (stage ^ 1) * STAGEW) * 4;
            const uint32_t vbn = kbn + KT * FST * 4;
            #pragma unroll
            for (int i = 0; i < 4; i++) {
                const int row = qrow + 16 * i;
                const size_t g = (size_t)(j0 + KT + row) * (2 * NINNER) + qc4;
                cpa16(kbn + (uint32_t)(row * FST + qc4) * 4, &Kb[g]);
                cpa16(vbn + (uint32_t)(row * VST + qc4) * 4, &Vb[g]);
            }
            CP_COMMIT();
            asm volatile("cp.async.wait_group 1;" ::: "memory");  // tile j done
        } else {
            asm volatile("cp.async.wait_group 0;" ::: "memory");
        }
        __syncthreads();   // tile j visible to all warps

        const uint32_t* sK = smf + SQW + stage * STAGEW;
        const uint32_t* sV = sK + KT * FST;

        // S = Q @ K^T  (16 rows x 64 keys per warp)
        float s[8][4] = {};
        #pragma unroll
        for (int ks = 0; ks < 8; ks++) {
            #pragma unroll
            for (int jn = 0; jn < 8; jn++) {
                const int kb = (jn * 8 + gid) * FST + ks * 8 + tig;
                mma8(s[jn], qf[ks], sK[kb], sK[kb + 4]);
            }
        }

        // online softmax (rows gid -> c0,c1 ; gid+8 -> c2,c3)
        float mx0 = -INFINITY, mx1 = -INFINITY;
        #pragma unroll
        for (int jn = 0; jn < 8; jn++) {
            mx0 = fmaxf(mx0, fmaxf(s[jn][0], s[jn][1]));
            mx1 = fmaxf(mx1, fmaxf(s[jn][2], s[jn][3]));
        }
        mx0 = fmaxf(mx0, __shfl_xor_sync(0xffffffffu, mx0, 1));
        mx0 = fmaxf(mx0, __shfl_xor_sync(0xffffffffu, mx0, 2));
        mx1 = fmaxf(mx1, __shfl_xor_sync(0xffffffffu, mx1, 1));
        mx1 = fmaxf(mx1, __shfl_xor_sync(0xffffffffu, mx1, 2));

        const float mn0 = fmaxf(mr0, mx0);
        const float mn1 = fmaxf(mr1, mx1);
        const float al0 = __expf(mr0 - mn0);
        const float al1 = __expf(mr1 - mn1);
        mr0 = mn0; mr1 = mn1;

        float rs0 = 0.f, rs1 = 0.f;
        {
            const int pb0 = (wrow + gid) * FST + 2 * tig;
            #pragma unroll
            for (int jn = 0; jn < 8; jn++) {
                const float p0 = __expf(s[jn][0] - mn0);
                const float p1 = __expf(s[jn][1] - mn0);
                const float p2 = __expf(s[jn][2] - mn1);
                const float p3 = __expf(s[jn][3] - mn1);
                rs0 += p0 + p1;
                rs1 += p2 + p3;
                uint2 w0 = { f2tf32(p0), f2tf32(p1) };
                uint2 w1 = { f2tf32(p2), f2tf32(p3) };
                *(uint2*)&sQ[pb0 + jn * 8]           = w0;   // sP overlays sQ
                *(uint2*)&sQ[pb0 + 8 * FST + jn * 8] = w1;
            }
        }
        rs0 += __shfl_xor_sync(0xffffffffu, rs0, 1);
        rs0 += __shfl_xor_sync(0xffffffffu, rs0, 2);
        rs1 += __shfl_xor_sync(0xffffffffu, rs1, 1);
        rs1 += __shfl_xor_sync(0xffffffffu, rs1, 2);
        lr0 = lr0 * al0 + rs0;
        lr1 = lr1 * al1 + rs1;

        #pragma unroll
        for (int dt = 0; dt < 8; dt++) {
            o[dt][0] *= al0; o[dt][1] *= al0;
            o[dt][2] *= al1; o[dt][3] *= al1;
        }
        __syncwarp();   // P rows are warp-private

        // O += P @ V
        #pragma unroll
        for (int ks = 0; ks < 8; ks++) {
            uint32_t pa[4];
            const int base = (wrow + gid) * FST + ks * 8 + tig;
            pa[0] = sQ[base];
            pa[1] = sQ[base + 8 * FST];
            pa[2] = sQ[base + 4];
            pa[3] = sQ[base + 8 * FST + 4];
            #pragma unroll
            for (int dt = 0; dt < 8; dt++) {
                const int vb = (ks * 8 + tig) * VST + dt * 8 + gid;
                mma8(o[dt], pa, sV[vb], sV[vb + 4 * VST]);
            }
        }
        stage ^= 1;
    }

    // epilogue
    const float inv0 = 1.0f / lr0;
    const float inv1 = 1.0f / lr1;
    const int r0 = q0 + wrow + gid;
    #pragma unroll
    for (int dt = 0; dt < 8; dt++) {
        const int col = dt * 8 + 2 * tig;
        float2 v0 = { o[dt][0] * inv0, o[dt][1] * inv0 };
        float2 v1 = { o[dt][2] * inv1, o[dt][3] * inv1 };
        *(float2*)&Ob[(size_t)r0 * NINNER + col]       = v0;
        *(float2*)&Ob[(size_t)(r0 + 8) * NINNER + col] = v1;
    }
}

// ===========================================================================
extern "C" void kernel_launch(void* const* d_in, const int* in_sizes, int n_in,
                              void* d_out, int out_size)
{
    const float* X   = (const float*)d_in[0];
    const float* Wq  = (const float*)d_in[1];
    const float* Wkv = (const float*)d_in[2];
    const float* Wo  = (const float*)d_in[3];
    const float* bo  = (const float*)d_in[4];
    float* out = (float*)d_out;

    float *Qb, *KVb, *Ab, *WqT, *WkvT, *WoT;
    cudaGetSymbolAddress((void**)&Qb,   g_Q);
    cudaGetSymbolAddress((void**)&KVb,  g_KV);
    cudaGetSymbolAddress((void**)&Ab,   g_A);
    cudaGetSymbolAddress((void**)&WqT,  g_WqT);
    cudaGetSymbolAddress((void**)&WkvT, g_WkvT);
    cudaGetSymbolAddress((void**)&WoT,  g_WoT);

    cudaFuncSetAttribute(gemm_mma, cudaFuncAttributeMaxDynamicSharedMemorySize,
                         GEMM_SMEM_BYTES);
    cudaFuncSetAttribute(flash_mma, cudaFuncAttributeMaxDynamicSharedMemorySize,
                         FLASH_SMEM_BYTES);

    dim3 tb(32, 8);
    // WqT carries the 1/sqrt(dh)=0.125 softmax scale (exact power-of-2)
    transpose_kernel<<<dim3(NINNER / 32, DMODEL / 32), tb>>>(Wq,  WqT,  DMODEL, NINNER, 0.125f);
    transpose_kernel<<<dim3(2 * NINNER / 32, DMODEL / 32), tb>>>(Wkv, WkvT, DMODEL, 2 * NINNER, 1.0f);
    transpose_kernel<<<dim3(DMODEL / 32, NINNER / 32), tb>>>(Wo,  WoT,  NINNER, DMODEL, 1.0f);

    // Q = (X @ Wq)*0.125, tf32-rounded at store
    gemm_mma<<<dim3(NINNER / 128, MTOT / 128), 256, GEMM_SMEM_BYTES>>>(
        X, WqT, nullptr, Qb, MTOT, NINNER, DMODEL, 1);
    // KV = X @ Wkv, tf32-rounded at store
    gemm_mma<<<dim3(2 * NINNER / 128, MTOT / 128), 256, GEMM_SMEM_BYTES>>>(
        X, WkvT, nullptr, KVb, MTOT, 2 * NINNER, DMODEL, 1);
    // attention
    flash_mma<<<dim3(NSEQ / 128, NB * NH), 256, FLASH_SMEM_BYTES>>>(Qb, KVb, Ab);
    // out = A @ Wo + bo (full fp32 store)
    gemm_mma<<<dim3(DMODEL / 128, MTOT / 128), 256, GEMM_SMEM_BYTES>>>(
        Ab, WoT, bo, out, MTOT, DMODEL, NINNER, 0);
}

// round 15
// speedup vs baseline: 1.1062x; 1.0331x over previous
#include <cuda_runtime.h>
#include <math.h>
#include <stdint.h>

// Problem shape (fixed per reference)
#define NB     2
#define NSEQ   2048
#define DMODEL 1024
#define NINNER 1024
#define NH     16
#define NDH    64
#define MTOT   (NB * NSEQ)   // 4096

// Scratch (allocation-free rule: __device__ globals)
__device__ float g_Xr [MTOT * DMODEL];        // 16 MB  tf32-rounded X
__device__ float g_Q  [MTOT * NINNER];        // 16 MB  (pre-scaled, tf32-valued)
__device__ float g_KV [MTOT * 2 * NINNER];    // 32 MB  (tf32-valued)
__device__ float g_A  [MTOT * NINNER];        // 16 MB  (tf32-valued)
__device__ float g_WqT [NINNER * DMODEL];     // 4 MB   [N][K], scaled+rounded
__device__ float g_WkvT[2 * NINNER * DMODEL]; // 8 MB   [N][K], rounded
__device__ float g_WoT [DMODEL * NINNER];     // 4 MB   [N][K], rounded

// ===========================================================================
// Helpers (baseline PTX only — ptxas targets sm_103, no 'a' features)
// ===========================================================================
__device__ __forceinline__ uint32_t f2tf32(float x) {
    uint32_t u;
    asm("cvt.rna.tf32.f32 %0, %1;" : "=r"(u) : "f"(x));
    return u;
}
__device__ __forceinline__ uint32_t smem_u32(const void* p) {
    uint32_t a;
    asm("{ .reg .u64 t; cvta.to.shared.u64 t, %1; cvt.u32.u64 %0, t; }"
        : "=r"(a) : "l"(p));
    return a;
}
__device__ __forceinline__ void cpa16(uint32_t dst, const void* src) {
    asm volatile("cp.async.cg.shared.global [%0], [%1], 16;"
                 :: "r"(dst), "l"(src) : "memory");
}
#define CP_COMMIT() asm volatile("cp.async.commit_group;" ::: "memory")
#define CP_WAIT1()  asm volatile("cp.async.wait_group 1;" ::: "memory")
#define CP_WAIT0()  asm volatile("cp.async.wait_group 0;" ::: "memory")

// m16n8k8 tf32 mma, row.col, fp32 accumulate
__device__ __forceinline__ void mma8(float* d, const uint32_t* a,
                                     uint32_t b0, uint32_t b1) {
    asm volatile(
        "mma.sync.aligned.m16n8k8.row.col.f32.tf32.tf32.f32 "
        "{%0,%1,%2,%3}, {%4,%5,%6,%7}, {%8,%9}, {%0,%1,%2,%3};"
        : "+f"(d[0]), "+f"(d[1]), "+f"(d[2]), "+f"(d[3])
        : "r"(a[0]), "r"(a[1]), "r"(a[2]), "r"(a[3]), "r"(b0), "r"(b1));
}

// ===========================================================================
// elementwise tf32 round: out[i] = tf32(in[i])   (n multiple of 1024)
// ===========================================================================
__global__ __launch_bounds__(256) void round_kernel(
    const float* __restrict__ in, float* __restrict__ out, int n)
{
    const int i = (blockIdx.x * 256 + threadIdx.x) * 4;
    if (i < n) {
        float4 v = *(const float4*)&in[i];
        uint4 u = { f2tf32(v.x), f2tf32(v.y), f2tf32(v.z), f2tf32(v.w) };
        *(uint4*)&out[i] = u;
    }
}

// ===========================================================================
// 32x32 tiled transpose with scale + tf32 round: out[C,R] = tf32(in[R,C]^T*s)
// ===========================================================================
__global__ void transpose_kernel(const float* __restrict__ in,
                                 float* __restrict__ out, int R, int C,
                                 float scale) {
    __shared__ float t[32][33];
    const int bx = blockIdx.x * 32;
    const int by = blockIdx.y * 32;
    #pragma unroll
    for (int i = 0; i < 32; i += 8)
        t[threadIdx.y + i][threadIdx.x] =
            in[(size_t)(by + threadIdx.y + i) * C + bx + threadIdx.x] * scale;
    __syncthreads();
    #pragma unroll
    for (int i = 0; i < 32; i += 8)
        out[(size_t)(bx + threadIdx.y + i) * R + by + threadIdx.x] =
            __uint_as_float(f2tf32(t[threadIdx.x][threadIdx.y + i]));
}

// ===========================================================================
// tf32 mma.sync GEMM: C[M,N] = A[M,K] @ Bt[N,K]^T (+bias)
// 128x128x32 CTA tile, 8 warps. 3-stage cp.async pipeline (inputs are
// pre-rounded tf32-valued fp32 -> loader is pure cp.async, 1 barrier/iter).
// ===========================================================================
#define GST 36
#define GSTW (128 * GST)             // 4608 words per tile
#define GSTAGEW (2 * GSTW)           // 9216 words per stage (A+B)
#define GEMM_SMEM_BYTES (3 * GSTAGEW * 4)    // 110592

__global__ __launch_bounds__(256, 2) void gemm_mma(
    const float* __restrict__ A, const float* __restrict__ Bt,
    const float* __restrict__ bias, float* __restrict__ C,
    int M, int N, int K, int round_out)
{
    extern __shared__ uint32_t sm[];
    const uint32_t smb = smem_u32(sm);
    const int tid  = threadIdx.x;
    const int lane = tid & 31, wid = tid >> 5;
    const int gid  = lane >> 2, tig = lane & 3;
    const int warp_m = wid & 1, warp_n = wid >> 1;
    const int bm = blockIdx.y * 128;
    const int bn = blockIdx.x * 128;

    const int lrow = tid >> 3;
    const int lch  = (tid & 7) << 2;
    const float* Ap = A  + (size_t)(bm + lrow) * K + lch;
    const float* Bp = Bt + (size_t)(bn + lrow) * K + lch;
    const uint32_t dstoff = (uint32_t)(lrow * GST + lch) * 4;
    const int nkt = K / 32;

    // stage issuer
    #define G_ISSUE(st, k0) do {                                              \
        const uint32_t base_ = smb + (uint32_t)(st) * (GSTAGEW * 4);          \
        _Pragma("unroll")                                                     \
        for (int i_ = 0; i_ < 4; i_++) {                                      \
            cpa16(base_ + dstoff + (uint32_t)(i_ * 32 * GST * 4),             \
                  Ap + (size_t)(32 * i_) * K + (k0));                         \
            cpa16(base_ + (GSTW * 4) + dstoff + (uint32_t)(i_ * 32 * GST * 4),\
                  Bp + (size_t)(32 * i_) * K + (k0));                         \
        }                                                                     \
        CP_COMMIT();                                                          \
    } while (0)

    G_ISSUE(0, 0);
    G_ISSUE(1, 32);

    float acc[4][4][4] = {};

    for (int kt = 0; kt < nkt; kt++) {
        if (kt + 1 < nkt) { CP_WAIT1(); } else { CP_WAIT0(); }
        __syncthreads();                       // stage kt visible; stage kt-1
                                               // fully consumed by all warps
        if (kt + 2 < nkt) G_ISSUE((kt + 2) % 3, (kt + 2) * 32);

        const uint32_t* sA = sm + (kt % 3) * GSTAGEW;
        const uint32_t* sB = sA + GSTW;
        #pragma unroll
        for (int ks = 0; ks < 4; ks++) {
            const int col = ks * 8 + tig;
            uint32_t af[4][4];
            #pragma unroll
            for (int im = 0; im < 4; im++) {
                const int base = (warp_m * 64 + im * 16 + gid) * GST + col;
                af[im][0] = sA[base];
                af[im][1] = sA[base + 8 * GST];
                af[im][2] = sA[base + 4];
                af[im][3] = sA[base + 8 * GST + 4];
            }
            uint32_t bf[4][2];
            #pragma unroll
            for (int jn = 0; jn < 4; jn++) {
                const int nb = (warp_n * 32 + jn * 8 + gid) * GST + col;
                bf[jn][0] = sB[nb];
                bf[jn][1] = sB[nb + 4];
            }
            #pragma unroll
            for (int im = 0; im < 4; im++)
                #pragma unroll
                for (int jn = 0; jn < 4; jn++)
                    mma8(acc[im][jn], af[im], bf[jn][0], bf[jn][1]);
        }
    }
    #undef G_ISSUE

    #pragma unroll
    for (int im = 0; im < 4; im++) {
        const int row0 = bm + warp_m * 64 + im * 16 + gid;
        #pragma unroll
        for (int jn = 0; jn < 4; jn++) {
            const int col = bn + warp_n * 32 + jn * 8 + 2 * tig;
            float b0 = 0.f, b1 = 0.f;
            if (bias) { b0 = bias[col]; b1 = bias[col + 1]; }
            float2 v0 = { acc[im][jn][0] + b0, acc[im][jn][1] + b1 };
            float2 v1 = { acc[im][jn][2] + b0, acc[im][jn][3] + b1 };
            if (round_out) {
                v0.x = __uint_as_float(f2tf32(v0.x));
                v0.y = __uint_as_float(f2tf32(v0.y));
                v1.x = __uint_as_float(f2tf32(v1.x));
                v1.y = __uint_as_float(f2tf32(v1.y));
            }
            *(float2*)&C[(size_t)row0 * N + col]       = v0;
            *(float2*)&C[(size_t)(row0 + 8) * N + col] = v1;
        }
    }
}

// ===========================================================================
// tf32 mma.sync flash attention, cp.async double-buffered K/V.
// 256 threads (8 warps), CTA = 128 Q rows of one (b,h); warp = 16 rows.
// KT=64. Q pre-scaled by 0.125*log2(e) -> softmax uses exp2f.
// Softmax/PV interleaved in 4 chunks of 2 key-columns: exp+P-store(2jn),
// quad-local syncwarp, then the 2 matching PV k-steps -> MUFU overlaps
// LDS/HMMA instead of phase-aligned serial execution.
// Output stores tf32-rounded (producer-side rounding for out-proj GEMM).
// ===========================================================================
#define KT  64
#define FST 68
#define VST 72
#define SQW    (128 * FST)             // 8704 words
#define STAGEW (KT * FST + KT * VST)   // 8960 words
#define FLASH_SMEM_BYTES ((SQW + 2 * STAGEW) * 4)   // 106496

__global__ __launch_bounds__(256, 2) void flash_mma(
    const float* __restrict__ Q, const float* __restrict__ KV,
    float* __restrict__ O)
{
    extern __shared__ uint32_t smf[];
    uint32_t* sQ = smf;                 // becomes sP after Q frags hoisted
    const uint32_t smb = smem_u32(smf);

    const int tid  = threadIdx.x;
    const int lane = tid & 31, wid = tid >> 5;
    const int gid  = lane >> 2, tig = lane & 3;
    const int wrow = wid * 16;
    const int q0   = blockIdx.x * 128;
    const int bh   = blockIdx.y;
    const int b    = bh >> 4;
    const int h    = bh & 15;

    const float* Qb = Q  + (size_t)b * NSEQ * NINNER     + (size_t)h * NDH;
    const float* Kb = KV + (size_t)b * NSEQ * 2 * NINNER + (size_t)h * NDH;
    const float* Vb = Kb + NINNER;
    float*       Ob = O  + (size_t)b * NSEQ * NINNER     + (size_t)h * NDH;

    const int qrow = tid >> 4;
    const int qc4  = (tid & 15) << 2;

    // ---- prologue: async-copy Q (group 0), then K/V tile 0 (group 1) ----
    #pragma unroll
    for (int i = 0; i < 8; i++) {
        const int row = qrow + 16 * i;
        cpa16(smb + (uint32_t)(row * FST + qc4) * 4,
              &Qb[(size_t)(q0 + row) * NINNER + qc4]);
    }
    CP_COMMIT();
    {
        const uint32_t kb0 = smb + SQW * 4;
        const uint32_t vb0 = kb0 + KT * FST * 4;
        #pragma unroll
        for (int i = 0; i < 4; i++) {
            const int row = qrow + 16 * i;
            const size_t g = (size_t)row * (2 * NINNER) + qc4;
            cpa16(kb0 + (uint32_t)(row * FST + qc4) * 4, &Kb[g]);
            cpa16(vb0 + (uint32_t)(row * VST + qc4) * 4, &Vb[g]);
        }
    }
    CP_COMMIT();
    CP_WAIT1();                        // Q done
    __syncthreads();

    // hoist Q fragments for all 8 k-steps (warp's own 16 rows)
    uint32_t qf[8][4];
    {
        const int base = (wrow + gid) * FST;
        #pragma unroll
        for (int ks = 0; ks < 8; ks++) {
            const int w = ks * 8 + tig;
            qf[ks][0] = sQ[base + w];
            qf[ks][1] = sQ[base + 8 * FST + w];
            qf[ks][2] = sQ[base + w + 4];
            qf[ks][3] = sQ[base + 8 * FST + w + 4];
        }
    }

    float o[8][4] = {};
    float mr0 = -INFINITY, mr1 = -INFINITY, lr0 = 0.f, lr1 = 0.f;
    const unsigned qmask = 0xFu << (lane & 28);   // quad-local sync mask

    int stage = 0;
    for (int j0 = 0; j0 < NSEQ; j0 += KT) {
        __syncthreads();   // all warps done with buffer stage^1 (tile j-1)
        if (j0 + KT < NSEQ) {
            const uint32_t kbn = smb + (SQW + (stage ^ 1) * STAGEW) * 4;
            const uint32_t vbn = kbn + KT * FST * 4;
            #pragma unroll
            for (int i = 0; i < 4; i++) {
                const int row = qrow + 16 * i;
                const size_t g = (size_t)(j0 + KT + row) * (2 * NINNER) + qc4;
                cpa16(kbn + (uint32_t)(row * FST + qc4) * 4, &Kb[g]);
                cpa16(vbn + (uint32_t)(row * VST + qc4) * 4, &Vb[g]);
            }
            CP_COMMIT();
            CP_WAIT1();                // tile j done
        } else {
            CP_WAIT0();
        }
        __syncthreads();   // tile j visible to all warps

        const uint32_t* sK = smf + SQW + stage * STAGEW;
        const uint32_t* sV = sK + KT * FST;

        // S = Q @ K^T  (16 rows x 64 keys per warp)
        float s[8][4] = {};
        #pragma unroll
        for (int ks = 0; ks < 8; ks++) {
            #pragma unroll
            for (int jn = 0; jn < 8; jn++) {
                const int kb = (jn * 8 + gid) * FST + ks * 8 + tig;
                mma8(s[jn], qf[ks], sK[kb], sK[kb + 4]);
            }
        }

        // row max (rows gid -> c0,c1 ; gid+8 -> c2,c3)
        float mx0 = -INFINITY, mx1 = -INFINITY;
        #pragma unroll
        for (int jn = 0; jn < 8; jn++) {
            mx0 = fmaxf(mx0, fmaxf(s[jn][0], s[jn][1]));
            mx1 = fmaxf(mx1, fmaxf(s[jn][2], s[jn][3]));
        }
        mx0 = fmaxf(mx0, __shfl_xor_sync(0xffffffffu, mx0, 1));
        mx0 = fmaxf(mx0, __shfl_xor_sync(0xffffffffu, mx0, 2));
        mx1 = fmaxf(mx1, __shfl_xor_sync(0xffffffffu, mx1, 1));
        mx1 = fmaxf(mx1, __shfl_xor_sync(0xffffffffu, mx1, 2));

        const float mn0 = fmaxf(mr0, mx0);
        const float mn1 = fmaxf(mr1, mx1);
        const float al0 = exp2f(mr0 - mn0);
        const float al1 = exp2f(mr1 - mn1);
        mr0 = mn0; mr1 = mn1;

        // rescale O before any PV accumulation
        #pragma unroll
        for (int dt = 0; dt < 8; dt++) {
            o[dt][0] *= al0; o[dt][1] *= al0;
            o[dt][2] *= al1; o[dt][3] *= al1;
        }

        // interleaved softmax + PV, 4 chunks of 2 key-columns
        float rs0 = 0.f, rs1 = 0.f;
        const int pb0    = (wrow + gid) * FST + 2 * tig;
        const int pabase = (wrow + gid) * FST + tig;
        #pragma unroll
        for (int jp = 0; jp < 4; jp++) {
            #pragma unroll
            for (int u = 0; u < 2; u++) {
                const int jn = jp * 2 + u;
                const float p0 = exp2f(s[jn][0] - mn0);
                const float p1 = exp2f(s[jn][1] - mn0);
                const float p2 = exp2f(s[jn][2] - mn1);
                const float p3 = exp2f(s[jn][3] - mn1);
                rs0 += p0 + p1;
                rs1 += p2 + p3;
                uint2 w0 = { f2tf32(p0), f2tf32(p1) };
                uint2 w1 = { f2tf32(p2), f2tf32(p3) };
                *(uint2*)&sQ[pb0 + jn * 8]           = w0;   // sP overlays sQ
                *(uint2*)&sQ[pb0 + 8 * FST + jn * 8] = w1;
            }
            __syncwarp(qmask);          // P exchange is intra-quad
            #pragma unroll
            for (int u = 0; u < 2; u++) {
                const int ks = jp * 2 + u;
                uint32_t pa[4];
                const int base = pabase + ks * 8;
                pa[0] = sQ[base];
                pa[1] = sQ[base + 8 * FST];
                pa[2] = sQ[base + 4];
                pa[3] = sQ[base + 8 * FST + 4];
                #pragma unroll
                for (int dt = 0; dt < 8; dt++) {
                    const int vb = (ks * 8 + tig) * VST + dt * 8 + gid;
                    mma8(o[dt], pa, sV[vb], sV[vb + 4 * VST]);
                }
            }
        }
        rs0 += __shfl_xor_sync(0xffffffffu, rs0, 1);
        rs0 += __shfl_xor_sync(0xffffffffu, rs0, 2);
        rs1 += __shfl_xor_sync(0xffffffffu, rs1, 1);
        rs1 += __shfl_xor_sync(0xffffffffu, rs1, 2);
        lr0 = lr0 * al0 + rs0;
        lr1 = lr1 * al1 + rs1;

        stage ^= 1;
    }

    // epilogue (tf32-rounded stores: out-proj GEMM consumes raw)
    const float inv0 = 1.0f / lr0;
    const float inv1 = 1.0f / lr1;
    const int r0 = q0 + wrow + gid;
    #pragma unroll
    for (int dt = 0; dt < 8; dt++) {
        const int col = dt * 8 + 2 * tig;
        uint2 v0 = { f2tf32(o[dt][0] * inv0), f2tf32(o[dt][1] * inv0) };
        uint2 v1 = { f2tf32(o[dt][2] * inv1), f2tf32(o[dt][3] * inv1) };
        *(uint2*)&Ob[(size_t)r0 * NINNER + col]       = v0;
        *(uint2*)&Ob[(size_t)(r0 + 8) * NINNER + col] = v1;
    }
}

// ===========================================================================
extern "C" void kernel_launch(void* const* d_in, const int* in_sizes, int n_in,
                              void* d_out, int out_size)
{
    const float* X   = (const float*)d_in[0];
    const float* Wq  = (const float*)d_in[1];
    const float* Wkv = (const float*)d_in[2];
    const float* Wo  = (const float*)d_in[3];
    const float* bo  = (const float*)d_in[4];
    float* out = (float*)d_out;

    float *Xr, *Qb, *KVb, *Ab, *WqT, *WkvT, *WoT;
    cudaGetSymbolAddress((void**)&Xr,   g_Xr);
    cudaGetSymbolAddress((void**)&Qb,   g_Q);
    cudaGetSymbolAddress((void**)&KVb,  g_KV);
    cudaGetSymbolAddress((void**)&Ab,   g_A);
    cudaGetSymbolAddress((void**)&WqT,  g_WqT);
    cudaGetSymbolAddress((void**)&WkvT, g_WkvT);
    cudaGetSymbolAddress((void**)&WoT,  g_WoT);

    cudaFuncSetAttribute(gemm_mma, cudaFuncAttributeMaxDynamicSharedMemorySize,
                         GEMM_SMEM_BYTES);
    cudaFuncSetAttribute(flash_mma, cudaFuncAttributeMaxDynamicSharedMemorySize,
                         FLASH_SMEM_BYTES);

    // pre-round X to tf32 values (enables pure-cp.async GEMM loader)
    round_kernel<<<MTOT * DMODEL / 1024, 256>>>(X, Xr, MTOT * DMODEL);

    dim3 tb(32, 8);
    // WqT carries 0.125 * log2(e) so flash softmax can use exp2f
    transpose_kernel<<<dim3(NINNER / 32, DMODEL / 32), tb>>>(
        Wq,  WqT,  DMODEL, NINNER, 0.125f * 1.4426950408889634f);
    transpose_kernel<<<dim3(2 * NINNER / 32, DMODEL / 32), tb>>>(
        Wkv, WkvT, DMODEL, 2 * NINNER, 1.0f);
    transpose_kernel<<<dim3(DMODEL / 32, NINNER / 32), tb>>>(
        Wo,  WoT,  NINNER, DMODEL, 1.0f);

    // Q = (X @ Wq) * 0.125*log2e, tf32-rounded at store
    gemm_mma<<<dim3(NINNER / 128, MTOT / 128), 256, GEMM_SMEM_BYTES>>>(
        Xr, WqT, nullptr, Qb, MTOT, NINNER, DMODEL, 1);
    // KV = X @ Wkv, tf32-rounded at store
    gemm_mma<<<dim3(2 * NINNER / 128, MTOT / 128), 256, GEMM_SMEM_BYTES>>>(
        Xr, WkvT, nullptr, KVb, MTOT, 2 * NINNER, DMODEL, 1);
    // attention (stores tf32-rounded A)
    flash_mma<<<dim3(NSEQ / 128, NB * NH), 256, FLASH_SMEM_BYTES>>>(Qb, KVb, Ab);
    // out = A @ Wo + bo (full fp32 store)
    gemm_mma<<<dim3(DMODEL / 128, MTOT / 128), 256, GEMM_SMEM_BYTES>>>(
        Ab, WoT, bo, out, MTOT, DMODEL, NINNER, 0);
}